// round 12
// baseline (speedup 1.0000x reference)
#include <cuda_runtime.h>
#include <cuda_bf16.h>
#include <math_constants.h>
#include <cstdint>

#define DIM     128
#define QB      128
#define NB      64
#define NSPLIT  18
#define LSEL    8
#define SHORT   20
#define KSEL    10
#define MAXB    2048
#define MAXN    100000
#define MAXNP   100992
#define CAND    (NSPLIT * LSEL)
#define NT      256

// ---- dynamic smem layout ----
#define OFF_A    0            // 128x128 bf16 queries, swizzled       32KB
#define OFF_B0   32768        // candidate tile buf0 (64x256B)        16KB
#define OFF_B1   49152        // candidate tile buf1                  16KB
#define OFF_C0   65536        // 64 floats c[n] buf0
#define OFF_C1   65792        // 64 floats c[n] buf1
#define OFF_D    66048        // 128 x 64 fp32 keys (XOR-swizzled)    32KB
#define OFF_KEY  98816        // 256 * LSEL floats (private half-lists)
#define OFF_IDX  (OFF_KEY + NT * LSEL * 4)
#define SMEM_DYN (OFF_IDX + NT * LSEL * 4 + 128)

// ---------------- device scratch ----------------
__device__ float          g_wmax;
__device__ float          g_c[MAXNP];
__device__ __nv_bfloat16  g_Xbf[(size_t)MAXNP * DIM];
__device__ float          g_keys[(size_t)MAXB * CAND];
__device__ int            g_idxs[(size_t)MAXB * CAND];

// ---------------- helpers ----------------
__device__ __forceinline__ uint32_t smem_u32(const void* p) {
    uint32_t a;
    asm("{ .reg .u64 t; cvta.to.shared.u64 t, %1; cvt.u32.u64 %0, t; }" : "=r"(a) : "l"(p));
    return a;
}
__device__ __forceinline__ void ldsm4(uint32_t& r0, uint32_t& r1, uint32_t& r2, uint32_t& r3,
                                      uint32_t addr) {
    asm volatile("ldmatrix.sync.aligned.m8n8.x4.shared.b16 {%0,%1,%2,%3}, [%4];"
                 : "=r"(r0), "=r"(r1), "=r"(r2), "=r"(r3) : "r"(addr));
}
__device__ __forceinline__ void mma16816(float* c, const uint32_t* a, uint32_t b0, uint32_t b1) {
    asm volatile("mma.sync.aligned.m16n8k16.row.col.f32.bf16.bf16.f32 "
                 "{%0,%1,%2,%3}, {%4,%5,%6,%7}, {%8,%9}, {%0,%1,%2,%3};"
                 : "+f"(c[0]), "+f"(c[1]), "+f"(c[2]), "+f"(c[3])
                 : "r"(a[0]), "r"(a[1]), "r"(a[2]), "r"(a[3]), "r"(b0), "r"(b1));
}
__device__ __forceinline__ void cpa16(uint32_t dst, const void* src) {
    asm volatile("cp.async.cg.shared.global [%0], [%1], 16;"
                 :: "r"(dst), "l"((size_t)__cvta_generic_to_global(src)) : "memory");
}
__device__ __forceinline__ void cpa4(uint32_t dst, const void* src) {
    asm volatile("cp.async.ca.shared.global [%0], [%1], 4;"
                 :: "r"(dst), "l"((size_t)__cvta_generic_to_global(src)) : "memory");
}
#define CP_COMMIT() asm volatile("cp.async.commit_group;" ::: "memory")
#define CP_WAIT(n)  asm volatile("cp.async.wait_group %0;" :: "n"(n) : "memory")

__device__ __forceinline__ uint32_t bf2pack(float x, float y) {
    __nv_bfloat162 v = __floats2bfloat162_rn(x, y);
    return *(uint32_t*)&v;
}
// 5-bit bijection: bit0->0, bits1-2->3-4, bits3-4->1-2
__device__ __forceinline__ int perm5(int x) {
    return (x & 1) | ((x & 6) << 2) | (((x >> 3) & 3) << 1);
}

// ---------------- init / wmax ----------------
__global__ void init_kernel() { g_wmax = 0.0f; }

__global__ void wmax_kernel(const float* __restrict__ w, int n) {
    float m = 0.0f;
    for (int i = blockIdx.x * blockDim.x + threadIdx.x; i < n; i += gridDim.x * blockDim.x)
        m = fmaxf(m, w[i]);
    #pragma unroll
    for (int o = 16; o; o >>= 1) m = fmaxf(m, __shfl_xor_sync(0xffffffffu, m, o));
    __shared__ float sm[32];
    int lane = threadIdx.x & 31, wid = threadIdx.x >> 5;
    if (lane == 0) sm[wid] = m;
    __syncthreads();
    if (wid == 0) {
        m = (lane < (int)(blockDim.x >> 5)) ? sm[lane] : 0.0f;
        #pragma unroll
        for (int o = 16; o; o >>= 1) m = fmaxf(m, __shfl_xor_sync(0xffffffffu, m, o));
        if (lane == 0) atomicMax((int*)&g_wmax, __float_as_int(m));  // vals >= 0
    }
}

// ---------------- prep: c[n] + bf16 convert, padded tail ----------------
__global__ void prep_kernel(const float* __restrict__ X, const float* __restrict__ w,
                            int n, int padn) {
    int i = blockIdx.x * blockDim.x + threadIdx.x;
    if (i >= padn) return;
    __nv_bfloat162* dst = (__nv_bfloat162*)(g_Xbf + (size_t)i * DIM);
    if (i >= n) {
        for (int j = 0; j < DIM / 2; j++) dst[j] = __floats2bfloat162_rn(0.f, 0.f);
        g_c[i] = CUDART_INF_F;
        return;
    }
    const float4* xr = (const float4*)(X + (size_t)i * DIM);
    float s = 0.0f;
    #pragma unroll
    for (int j = 0; j < DIM / 4; j++) {
        float4 v = xr[j];
        s = fmaf(v.x, v.x, s); s = fmaf(v.y, v.y, s);
        s = fmaf(v.z, v.z, s); s = fmaf(v.w, v.w, s);
        dst[2 * j + 0] = __floats2bfloat162_rn(v.x, v.y);
        dst[2 * j + 1] = __floats2bfloat162_rn(v.z, v.w);
    }
    g_c[i] = s + (g_wmax - w[i]);
}

// insertion into sorted per-thread smem list
__device__ __forceinline__ void list_ins(float* mk, int* mi, float& thr, int& thrn,
                                         float key, int n) {
    int p = LSEL - 1;
    #pragma unroll 1
    while (p > 0 && (mk[p - 1] > key || (mk[p - 1] == key && mi[p - 1] > n))) {
        mk[p] = mk[p - 1]; mi[p] = mi[p - 1]; p--;
    }
    mk[p] = key; mi[p] = n;
    thr = mk[LSEL - 1]; thrn = mi[LSEL - 1];
}

// ---------------- main: M32N32 mma.sync GEMM + float2 staged top-LSEL ----
__global__ void __launch_bounds__(NT, 2)
topk_kernel(const float* __restrict__ xt, int per, int ntiles) {
    extern __shared__ unsigned char sraw[];
    unsigned char* s = sraw;
    const uint32_t sb = smem_u32(s);

    const int tid = threadIdx.x;
    const int l = tid & 31, wid = tid >> 5;
    const int wm = wid >> 1, wn = wid & 1;          // warp grid 4 x 2 (32 x 32 per warp)
    const int qbase = blockIdx.x * QB;
    const int split = blockIdx.y;
    const int sBeg = split * per;
    const int nEnd = sBeg + per;

    float* sD   = (float*)(s + OFF_D);
    float* sKey = (float*)(s + OFF_KEY);
    int*   sIdx = (int*)(s + OFF_IDX);

    // scan identity: thread owns query (tid & 127), col half (tid >> 7) of 32
    const int sq = tid & 127;
    const int vbase = (tid >> 7) << 5;              // 0 or 32
    const int permq = perm5(sq & 31);
    const int ppq = permq & ~1;                     // even part of perm
    const int sel = permq & 1;                      // component-swap bit
    float* mk = sKey + tid * LSEL;
    int*   mi = sIdx + tid * LSEL;
    #pragma unroll
    for (int j = 0; j < LSEL; j++) { mk[j] = CUDART_INF_F; mi[j] = 0x7fffffff; }
    float thr = CUDART_INF_F;
    int   thrn = 0x7fffffff;

    // ---- load query tile: fp32 -> bf16, swizzled rows of 256B ----
    {
        const int row = tid >> 1, half = tid & 1;
        const float4* src = (const float4*)(xt + (size_t)(qbase + row) * DIM) + half * 16;
        const uint32_t rbase = sb + OFF_A + row * 256;
        const int sw = (row & 7);
        #pragma unroll
        for (int i = 0; i < 8; i++) {
            float4 v0 = src[2 * i], v1 = src[2 * i + 1];
            uint4 pk = make_uint4(bf2pack(v0.x, v0.y), bf2pack(v0.z, v0.w),
                                  bf2pack(v1.x, v1.y), bf2pack(v1.z, v1.w));
            int c16 = half * 8 + i;
            uint32_t addr = rbase + (((uint32_t)(c16 ^ sw)) << 4);
            asm volatile("st.shared.v4.b32 [%0], {%1,%2,%3,%4};"
                         :: "r"(addr), "r"(pk.x), "r"(pk.y), "r"(pk.z), "r"(pk.w) : "memory");
        }
    }

    auto prefetch = [&](uint32_t boff, uint32_t coff, int nbase) {
        const unsigned char* gb = (const unsigned char*)g_Xbf + (size_t)nbase * 256;
        #pragma unroll
        for (int i = 0; i < 4; i++) {
            int chunk = tid + i * NT;               // 0..1023
            int row = chunk >> 4, c16 = chunk & 15;
            uint32_t dst = sb + boff + row * 256 + (((uint32_t)(c16 ^ (row & 7))) << 4);
            cpa16(dst, gb + row * 256 + c16 * 16);
        }
        if (tid < NB) cpa4(sb + coff + tid * 4, &g_c[nbase + tid]);
        CP_COMMIT();
    };
    prefetch(OFF_B0, OFF_C0, sBeg);

    const int arow = (l & 15);
    const int brow = ((l >> 4) << 3) + (l & 7);
    const int ac16 = (l >> 4);
    const int bc16 = (l >> 3) & 1;
    const int sw7 = (l & 7);

    for (int t = 0; t < ntiles; t++) {
        const int cur = t & 1;
        const uint32_t boff = cur ? OFF_B1 : OFF_B0;
        const uint32_t coff = cur ? OFF_C1 : OFF_C0;
        if (t + 1 < ntiles) {
            prefetch(cur ? OFF_B0 : OFF_B1, cur ? OFF_C0 : OFF_C1, sBeg + (t + 1) * NB);
            CP_WAIT(1);
        } else {
            CP_WAIT(0);
        }
        __syncthreads();   // B/C ready; orders prev scan-reads before this stage-writes

        float acc[2][4][4];
        #pragma unroll
        for (int a = 0; a < 2; a++)
            #pragma unroll
            for (int b = 0; b < 4; b++)
                #pragma unroll
                for (int c = 0; c < 4; c++) acc[a][b][c] = 0.0f;

        #pragma unroll
        for (int ks = 0; ks < 8; ks++) {
            uint32_t af[2][4];
            #pragma unroll
            for (int mt = 0; mt < 2; mt++) {
                uint32_t addr = sb + OFF_A + (wm * 32 + mt * 16 + arow) * 256 +
                                (((uint32_t)((ac16 + 2 * ks) ^ sw7)) << 4);
                ldsm4(af[mt][0], af[mt][1], af[mt][2], af[mt][3], addr);
            }
            uint32_t bf[2][4];
            #pragma unroll
            for (int pr = 0; pr < 2; pr++) {
                uint32_t addr = sb + boff + (wn * 32 + pr * 16 + brow) * 256 +
                                (((uint32_t)((bc16 + 2 * ks) ^ sw7)) << 4);
                ldsm4(bf[pr][0], bf[pr][1], bf[pr][2], bf[pr][3], addr);
            }
            #pragma unroll
            for (int mt = 0; mt < 2; mt++) {
                #pragma unroll
                for (int pr = 0; pr < 2; pr++) {
                    mma16816(acc[mt][2 * pr + 0], af[mt], bf[pr][0], bf[pr][1]);
                    mma16816(acc[mt][2 * pr + 1], af[mt], bf[pr][2], bf[pr][3]);
                }
            }
        }

        // ---- stage keys into sD as float2 pairs (XOR-perm swizzle) ----
        {
            const float* sC = (const float*)(s + coff);
            float cc[4][2];
            #pragma unroll
            for (int nt = 0; nt < 4; nt++) {
                const float2 cv = *(const float2*)(sC + wn * 32 + nt * 8 + ((l & 3) << 1));
                cc[nt][0] = cv.x; cc[nt][1] = cv.y;
            }
            #pragma unroll
            for (int mt = 0; mt < 2; mt++) {
                #pragma unroll
                for (int h = 0; h < 2; h++) {
                    const int q = wm * 32 + mt * 16 + (l >> 2) + (h << 3);
                    const int pq = perm5(q & 31);
                    const int pq2 = pq & ~1;
                    const bool sw = (pq & 1) != 0;
                    float* rowq = sD + q * 64;
                    #pragma unroll
                    for (int nt = 0; nt < 4; nt++) {
                        const int v = wn * 32 + nt * 8 + ((l & 3) << 1);
                        const float k0 = fmaf(-2.0f, acc[mt][nt][2 * h + 0], cc[nt][0]);
                        const float k1 = fmaf(-2.0f, acc[mt][nt][2 * h + 1], cc[nt][1]);
                        float2 val = sw ? make_float2(k1, k0) : make_float2(k0, k1);
                        *(float2*)(rowq + (v ^ pq2)) = val;
                    }
                }
            }
        }
        __syncthreads();

        // ---- per-query scan (float2): thread owns query sq, cols [vbase, vbase+32) ----
        {
            const int nbase = sBeg + t * NB;
            const float* sDq = sD + sq * 64;
            #pragma unroll 8
            for (int v2 = vbase; v2 < vbase + 32; v2 += 2) {
                const float2 kk = *(const float2*)(sDq + (v2 ^ ppq));
                const float k0 = sel ? kk.y : kk.x;   // key for n = nbase+v2
                const float k1 = sel ? kk.x : kk.y;   // key for n = nbase+v2+1
                const int n0 = nbase + v2;
                if ((k0 < thr || (k0 == thr && n0 < thrn)) && n0 < nEnd)
                    list_ins(mk, mi, thr, thrn, k0, n0);
                const int n1 = n0 + 1;
                if ((k1 < thr || (k1 == thr && n1 < thrn)) && n1 < nEnd)
                    list_ins(mk, mi, thr, thrn, k1, n1);
            }
        }
        // (loop-top __syncthreads orders scan reads before next tile's staging)
    }
    __syncthreads();

    // ---- 2-way merge of sorted half-lists; write per-query result ----
    if (tid < QB) {
        const float* ka = sKey + tid * LSEL;         const int* na = sIdx + tid * LSEL;
        const float* kb = sKey + (tid + 128) * LSEL; const int* nb = sIdx + (tid + 128) * LSEL;
        size_t o = ((size_t)(qbase + tid) * NSPLIT + split) * LSEL;
        int ia = 0, ib = 0;
        #pragma unroll
        for (int j = 0; j < LSEL; j++) {
            bool ta = (ka[ia] < kb[ib]) || (ka[ia] == kb[ib] && na[ia] <= nb[ib]);
            if (ta) { g_keys[o + j] = ka[ia]; g_idxs[o + j] = na[ia]; ia++; }
            else    { g_keys[o + j] = kb[ib]; g_idxs[o + j] = nb[ib]; ib++; }
        }
    }
}

// ---------------- merge: approx top-20 of union -> exact rescore -> argmax ----
__global__ void __launch_bounds__(128)
merge_kernel(const float* __restrict__ xt, const float* __restrict__ X,
             const float* __restrict__ w, float* __restrict__ out, int B, int out_size) {
    __shared__ float sk[4][CAND];
    __shared__ int   si[4][CAND];
    __shared__ int   sn[4][SHORT];
    const int wid = threadIdx.x >> 5, lane = threadIdx.x & 31;
    const int b = blockIdx.x * 4 + wid;
    if (b >= B) return;

    for (int i = lane; i < CAND; i += 32) {
        sk[wid][i] = g_keys[(size_t)b * CAND + i];
        si[wid][i] = g_idxs[(size_t)b * CAND + i];
    }
    __syncwarp();

    for (int t = 0; t < SHORT; t++) {
        float bk = CUDART_INF_F; int bi = 0x7fffffff; int bp = -1;
        for (int i = lane; i < CAND; i += 32) {
            float kk = sk[wid][i]; int ii = si[wid][i];
            if (kk < bk || (kk == bk && ii < bi)) { bk = kk; bi = ii; bp = i; }
        }
        #pragma unroll
        for (int o = 16; o; o >>= 1) {
            float ok = __shfl_xor_sync(0xffffffffu, bk, o);
            int   oi = __shfl_xor_sync(0xffffffffu, bi, o);
            int   op = __shfl_xor_sync(0xffffffffu, bp, o);
            if (ok < bk || (ok == bk && oi < bi)) { bk = ok; bi = oi; bp = op; }
        }
        if (lane == 0) { sn[wid][t] = bi; sk[wid][bp] = CUDART_INF_F; }
        __syncwarp();
    }

    const float4 qv = *(const float4*)(xt + (size_t)b * DIM + lane * 4);
    float q2 = qv.x * qv.x + qv.y * qv.y + qv.z * qv.z + qv.w * qv.w;
    #pragma unroll
    for (int o = 16; o; o >>= 1) q2 += __shfl_xor_sync(0xffffffffu, q2, o);

    float keyA[SHORT], ddA[SHORT], wA[SHORT]; int nA[SHORT];
    const float wmax = g_wmax;
    for (int t = 0; t < SHORT; t++) {
        const int n = sn[wid][t];
        const float4 xv = *(const float4*)(X + (size_t)n * DIM + lane * 4);
        float dp = 0.0f, xp = 0.0f;
        dp = fmaf(qv.x, xv.x, dp); dp = fmaf(qv.y, xv.y, dp);
        dp = fmaf(qv.z, xv.z, dp); dp = fmaf(qv.w, xv.w, dp);
        xp = fmaf(xv.x, xv.x, xp); xp = fmaf(xv.y, xv.y, xp);
        xp = fmaf(xv.z, xv.z, xp); xp = fmaf(xv.w, xv.w, xp);
        #pragma unroll
        for (int o = 16; o; o >>= 1) {
            dp += __shfl_xor_sync(0xffffffffu, dp, o);
            xp += __shfl_xor_sync(0xffffffffu, xp, o);
        }
        if (lane == 0) {
            const float wn = w[n];
            const float dd = q2 - 2.0f * dp + xp;
            ddA[t] = dd; keyA[t] = dd + (wmax - wn); wA[t] = wn; nA[t] = n;
        }
    }

    if (lane == 0) {
        bool used[SHORT];
        #pragma unroll
        for (int t = 0; t < SHORT; t++) used[t] = false;
        float bestF = -CUDART_INF_F; int bestI = 0;
        for (int r = 0; r < KSEL; r++) {
            int pm = -1; float mkv = CUDART_INF_F; int miv = 0x7fffffff;
            for (int t = 0; t < SHORT; t++) {
                if (!used[t] && (keyA[t] < mkv || (keyA[t] == mkv && nA[t] < miv))) {
                    mkv = keyA[t]; miv = nA[t]; pm = t;
                }
            }
            if (pm < 0) break;
            used[pm] = true;
            const float f = wA[pm] - sqrtf(fmaxf(ddA[pm], 0.0f));
            if (f > bestF) { bestF = f; bestI = nA[pm]; }
        }
        out[b] = bestF;
        if (out_size >= 2 * B) out[B + b] = (float)bestI;
    }
}

// ---------------- entry ----------------
extern "C" void kernel_launch(void* const* d_in, const int* in_sizes, int n_in,
                              void* d_out, int out_size) {
    const float* xt = (const float*)d_in[0];
    const float* X  = (const float*)d_in[1];
    const float* w  = (const float*)d_in[2];
    const int B = in_sizes[0] / DIM;
    const int N = in_sizes[1] / DIM;

    const int per = (N + NSPLIT - 1) / NSPLIT;
    const int ntiles = (per + NB - 1) / NB;
    int padn = (NSPLIT - 1) * per + ntiles * NB;
    if (padn > MAXNP) padn = MAXNP;

    static bool once = false;
    if (!once) {
        cudaFuncSetAttribute(topk_kernel, cudaFuncAttributeMaxDynamicSharedMemorySize, SMEM_DYN);
        once = true;
    }

    init_kernel<<<1, 1>>>();
    wmax_kernel<<<160, 256>>>(w, N);
    prep_kernel<<<(padn + 255) / 256, 256>>>(X, w, N, padn);
    dim3 grid(B / QB, NSPLIT);
    topk_kernel<<<grid, NT, SMEM_DYN>>>(xt, per, ntiles);
    merge_kernel<<<(B + 3) / 4, 128>>>(xt, X, w, (float*)d_out, B, out_size);
}

// round 13
// speedup vs baseline: 1.0817x; 1.0817x over previous
#include <cuda_runtime.h>
#include <cuda_bf16.h>
#include <math_constants.h>
#include <cstdint>

#define DIM     128
#define QB      128
#define NB      64
#define NSPLIT  18
#define LSUB    5            // per-(query,thread) private sub-list
#define LSEL    8            // per-split output entries per query
#define SHORT   20
#define KSEL    10
#define MAXB    2048
#define MAXN    100000
#define MAXNP   100992
#define CAND    (NSPLIT * LSEL)
#define NT      256

// ---- dynamic smem layout ----
#define OFF_A    0            // 128x128 bf16 queries, swizzled       32KB
#define OFF_B0   32768        // candidate tile buf0 (64x256B)        16KB
#define OFF_B1   49152        // candidate tile buf1                  16KB
#define OFF_C0   65536        // 64 floats c[n] buf0
#define OFF_C1   65792        // 64 floats c[n] buf1
#define OFF_LK   66048        // 1024 lists x LSUB keys (fp32)        20KB
#define OFF_LI   (OFF_LK + 1024 * LSUB * 4)      // 1024 x LSUB u16   10KB
#define SMEM_DYN (OFF_LI + 1024 * LSUB * 2 + 128)

// ---------------- device scratch ----------------
__device__ float          g_wmax;
__device__ float          g_c[MAXNP];
__device__ __nv_bfloat16  g_Xbf[(size_t)MAXNP * DIM];
__device__ float          g_keys[(size_t)MAXB * CAND];
__device__ int            g_idxs[(size_t)MAXB * CAND];

// ---------------- helpers ----------------
__device__ __forceinline__ uint32_t smem_u32(const void* p) {
    uint32_t a;
    asm("{ .reg .u64 t; cvta.to.shared.u64 t, %1; cvt.u32.u64 %0, t; }" : "=r"(a) : "l"(p));
    return a;
}
__device__ __forceinline__ void ldsm4(uint32_t& r0, uint32_t& r1, uint32_t& r2, uint32_t& r3,
                                      uint32_t addr) {
    asm volatile("ldmatrix.sync.aligned.m8n8.x4.shared.b16 {%0,%1,%2,%3}, [%4];"
                 : "=r"(r0), "=r"(r1), "=r"(r2), "=r"(r3) : "r"(addr));
}
__device__ __forceinline__ void mma16816(float* c, const uint32_t* a, uint32_t b0, uint32_t b1) {
    asm volatile("mma.sync.aligned.m16n8k16.row.col.f32.bf16.bf16.f32 "
                 "{%0,%1,%2,%3}, {%4,%5,%6,%7}, {%8,%9}, {%0,%1,%2,%3};"
                 : "+f"(c[0]), "+f"(c[1]), "+f"(c[2]), "+f"(c[3])
                 : "r"(a[0]), "r"(a[1]), "r"(a[2]), "r"(a[3]), "r"(b0), "r"(b1));
}
__device__ __forceinline__ void cpa16(uint32_t dst, const void* src) {
    asm volatile("cp.async.cg.shared.global [%0], [%1], 16;"
                 :: "r"(dst), "l"((size_t)__cvta_generic_to_global(src)) : "memory");
}
__device__ __forceinline__ void cpa4(uint32_t dst, const void* src) {
    asm volatile("cp.async.ca.shared.global [%0], [%1], 4;"
                 :: "r"(dst), "l"((size_t)__cvta_generic_to_global(src)) : "memory");
}
#define CP_COMMIT() asm volatile("cp.async.commit_group;" ::: "memory")
#define CP_WAIT(n)  asm volatile("cp.async.wait_group %0;" :: "n"(n) : "memory")

__device__ __forceinline__ uint32_t bf2pack(float x, float y) {
    __nv_bfloat162 v = __floats2bfloat162_rn(x, y);
    return *(uint32_t*)&v;
}

// ---------------- init / wmax ----------------
__global__ void init_kernel() { g_wmax = 0.0f; }

__global__ void wmax_kernel(const float* __restrict__ w, int n) {
    float m = 0.0f;
    for (int i = blockIdx.x * blockDim.x + threadIdx.x; i < n; i += gridDim.x * blockDim.x)
        m = fmaxf(m, w[i]);
    #pragma unroll
    for (int o = 16; o; o >>= 1) m = fmaxf(m, __shfl_xor_sync(0xffffffffu, m, o));
    __shared__ float sm[32];
    int lane = threadIdx.x & 31, wid = threadIdx.x >> 5;
    if (lane == 0) sm[wid] = m;
    __syncthreads();
    if (wid == 0) {
        m = (lane < (int)(blockDim.x >> 5)) ? sm[lane] : 0.0f;
        #pragma unroll
        for (int o = 16; o; o >>= 1) m = fmaxf(m, __shfl_xor_sync(0xffffffffu, m, o));
        if (lane == 0) atomicMax((int*)&g_wmax, __float_as_int(m));  // vals >= 0
    }
}

// ---------------- prep: c[n] + bf16 convert, padded tail ----------------
__global__ void prep_kernel(const float* __restrict__ X, const float* __restrict__ w,
                            int n, int padn) {
    int i = blockIdx.x * blockDim.x + threadIdx.x;
    if (i >= padn) return;
    __nv_bfloat162* dst = (__nv_bfloat162*)(g_Xbf + (size_t)i * DIM);
    if (i >= n) {
        for (int j = 0; j < DIM / 2; j++) dst[j] = __floats2bfloat162_rn(0.f, 0.f);
        g_c[i] = CUDART_INF_F;
        return;
    }
    const float4* xr = (const float4*)(X + (size_t)i * DIM);
    float s = 0.0f;
    #pragma unroll
    for (int j = 0; j < DIM / 4; j++) {
        float4 v = xr[j];
        s = fmaf(v.x, v.x, s); s = fmaf(v.y, v.y, s);
        s = fmaf(v.z, v.z, s); s = fmaf(v.w, v.w, s);
        dst[2 * j + 0] = __floats2bfloat162_rn(v.x, v.y);
        dst[2 * j + 1] = __floats2bfloat162_rn(v.z, v.w);
    }
    g_c[i] = s + (g_wmax - w[i]);
}

// private sorted sub-list insert (stream is ascending code => stable ties)
__device__ __forceinline__ void sub_ins(float* LK, unsigned short* LI, int base,
                                        float key, int code) {
    int p = LSUB - 1;
    #pragma unroll 1
    while (p > 0 && LK[base + p - 1] > key) {
        LK[base + p] = LK[base + p - 1];
        LI[base + p] = LI[base + p - 1];
        p--;
    }
    LK[base + p] = key;
    LI[base + p] = (unsigned short)code;
}

// ---------------- main: M32N32 mma.sync GEMM + private-list top-k ----------------
__global__ void __launch_bounds__(NT, 2)
topk_kernel(const float* __restrict__ xt, int per, int ntiles) {
    extern __shared__ unsigned char sraw[];
    unsigned char* s = sraw;
    const uint32_t sb = smem_u32(s);

    const int tid = threadIdx.x;
    const int l = tid & 31, wid = tid >> 5;
    const int wm = wid >> 1, wn = wid & 1;          // warp grid 4 x 2 (32 x 32 per warp)
    const int qbase = blockIdx.x * QB;
    const int split = blockIdx.y;
    const int sBeg = split * per;

    float*          LK = (float*)(s + OFF_LK);
    unsigned short* LI = (unsigned short*)(s + OFF_LI);

    // init private lists (1024 x LSUB)
    for (int i = tid; i < 1024 * LSUB; i += NT) { LK[i] = CUDART_INF_F; LI[i] = 0xffff; }

    // ---- load query tile: fp32 -> bf16, swizzled rows of 256B ----
    {
        const int row = tid >> 1, half = tid & 1;
        const float4* src = (const float4*)(xt + (size_t)(qbase + row) * DIM) + half * 16;
        const uint32_t rbase = sb + OFF_A + row * 256;
        const int sw = (row & 7);
        #pragma unroll
        for (int i = 0; i < 8; i++) {
            float4 v0 = src[2 * i], v1 = src[2 * i + 1];
            uint4 pk = make_uint4(bf2pack(v0.x, v0.y), bf2pack(v0.z, v0.w),
                                  bf2pack(v1.x, v1.y), bf2pack(v1.z, v1.w));
            int c16 = half * 8 + i;
            uint32_t addr = rbase + (((uint32_t)(c16 ^ sw)) << 4);
            asm volatile("st.shared.v4.b32 [%0], {%1,%2,%3,%4};"
                         :: "r"(addr), "r"(pk.x), "r"(pk.y), "r"(pk.z), "r"(pk.w) : "memory");
        }
    }

    auto prefetch = [&](uint32_t boff, uint32_t coff, int nbase) {
        const unsigned char* gb = (const unsigned char*)g_Xbf + (size_t)nbase * 256;
        #pragma unroll
        for (int i = 0; i < 4; i++) {
            int chunk = tid + i * NT;               // 0..1023
            int row = chunk >> 4, c16 = chunk & 15;
            uint32_t dst = sb + boff + row * 256 + (((uint32_t)(c16 ^ (row & 7))) << 4);
            cpa16(dst, gb + row * 256 + c16 * 16);
        }
        if (tid < NB) cpa4(sb + coff + tid * 4, &g_c[nbase + tid]);
        CP_COMMIT();
    };
    prefetch(OFF_B0, OFF_C0, sBeg);

    const int arow = (l & 15);
    const int brow = ((l >> 4) << 3) + (l & 7);
    const int ac16 = (l >> 4);
    const int bc16 = (l >> 3) & 1;
    const int sw7 = (l & 7);

    // private list bases: listid = q*8 + (wn*4 + (l&3)); q = wm*32+mt*16+(l>>2)+h*8
    const int lbase0 = ((wm * 32 + (l >> 2)) * 8 + wn * 4 + (l & 3)) * LSUB;
    float thr[4] = {CUDART_INF_F, CUDART_INF_F, CUDART_INF_F, CUDART_INF_F};

    for (int t = 0; t < ntiles; t++) {
        const int cur = t & 1;
        const uint32_t boff = cur ? OFF_B1 : OFF_B0;
        const uint32_t coff = cur ? OFF_C1 : OFF_C0;
        CP_WAIT(0);        // own copies of tile t complete
        __syncthreads();   // publish copies; all warps done with prev iteration
        if (t + 1 < ntiles)
            prefetch(cur ? OFF_B0 : OFF_B1, cur ? OFF_C0 : OFF_C1, sBeg + (t + 1) * NB);

        float acc[2][4][4];
        #pragma unroll
        for (int a = 0; a < 2; a++)
            #pragma unroll
            for (int b = 0; b < 4; b++)
                #pragma unroll
                for (int c = 0; c < 4; c++) acc[a][b][c] = 0.0f;

        #pragma unroll
        for (int ks = 0; ks < 8; ks++) {
            uint32_t af[2][4];
            #pragma unroll
            for (int mt = 0; mt < 2; mt++) {
                uint32_t addr = sb + OFF_A + (wm * 32 + mt * 16 + arow) * 256 +
                                (((uint32_t)((ac16 + 2 * ks) ^ sw7)) << 4);
                ldsm4(af[mt][0], af[mt][1], af[mt][2], af[mt][3], addr);
            }
            uint32_t bf[2][4];
            #pragma unroll
            for (int pr = 0; pr < 2; pr++) {
                uint32_t addr = sb + boff + (wn * 32 + pr * 16 + brow) * 256 +
                                (((uint32_t)((bc16 + 2 * ks) ^ sw7)) << 4);
                ldsm4(bf[pr][0], bf[pr][1], bf[pr][2], bf[pr][3], addr);
            }
            #pragma unroll
            for (int mt = 0; mt < 2; mt++) {
                #pragma unroll
                for (int pr = 0; pr < 2; pr++) {
                    mma16816(acc[mt][2 * pr + 0], af[mt], bf[pr][0], bf[pr][1]);
                    mma16816(acc[mt][2 * pr + 1], af[mt], bf[pr][2], bf[pr][3]);
                }
            }
        }

        // ---- epilogue: threshold filter + private sub-list inserts ----
        {
            const float* sC = (const float*)(s + coff);
            float cc[4][2];
            #pragma unroll
            for (int nt = 0; nt < 4; nt++) {
                const float2 cv = *(const float2*)(sC + wn * 32 + nt * 8 + ((l & 3) << 1));
                cc[nt][0] = cv.x; cc[nt][1] = cv.y;
            }
            const int codeBase = t * NB;
            const bool tail = (t == ntiles - 1);
            #pragma unroll
            for (int mt = 0; mt < 2; mt++) {
                #pragma unroll
                for (int h = 0; h < 2; h++) {
                    const int li = mt * 2 + h;
                    const int lbase = lbase0 + mt * (16 * 8 * LSUB) + h * (8 * 8 * LSUB);
                    float th = thr[li];
                    #pragma unroll
                    for (int nt = 0; nt < 4; nt++) {
                        const int v0 = wn * 32 + nt * 8 + ((l & 3) << 1);
                        const float k0 = fmaf(-2.0f, acc[mt][nt][2 * h + 0], cc[nt][0]);
                        const float k1 = fmaf(-2.0f, acc[mt][nt][2 * h + 1], cc[nt][1]);
                        if (k0 < th) {
                            const int code = codeBase + v0;
                            if (!tail || code < per) {
                                sub_ins(LK, LI, lbase, k0, code);
                                th = LK[lbase + LSUB - 1];
                            }
                        }
                        if (k1 < th) {
                            const int code = codeBase + v0 + 1;
                            if (!tail || code < per) {
                                sub_ins(LK, LI, lbase, k1, code);
                                th = LK[lbase + LSUB - 1];
                            }
                        }
                    }
                    thr[li] = th;
                }
            }
        }
    }
    __syncthreads();

    // ---- owner thread: 8-way merge of sub-lists -> top-LSEL per query ----
    if (tid < QB) {
        const int q = tid;
        float head[8]; int hcode[8]; int ptr[8];
        #pragma unroll
        for (int c = 0; c < 8; c++) {
            const int b = (q * 8 + c) * LSUB;
            head[c] = LK[b]; hcode[c] = LI[b]; ptr[c] = 0;
        }
        size_t o = ((size_t)(qbase + q) * NSPLIT + split) * LSEL;
        #pragma unroll 1
        for (int j = 0; j < LSEL; j++) {
            int bc = 0; float bk = head[0]; int bi = hcode[0];
            #pragma unroll
            for (int c = 1; c < 8; c++) {
                if (head[c] < bk || (head[c] == bk && hcode[c] < bi)) {
                    bk = head[c]; bi = hcode[c]; bc = c;
                }
            }
            g_keys[o + j] = bk;
            g_idxs[o + j] = (bk == CUDART_INF_F) ? 0x7fffffff : (sBeg + bi);
            ptr[bc]++;
            if (ptr[bc] < LSUB) {
                const int b = (q * 8 + bc) * LSUB + ptr[bc];
                head[bc] = LK[b]; hcode[bc] = LI[b];
            } else {
                head[bc] = CUDART_INF_F; hcode[bc] = 0x7fffffff;
            }
        }
    }
}

// ---------------- merge: approx top-20 of union -> exact rescore -> argmax ----
__global__ void __launch_bounds__(128)
merge_kernel(const float* __restrict__ xt, const float* __restrict__ X,
             const float* __restrict__ w, float* __restrict__ out, int B, int out_size) {
    __shared__ float sk[4][CAND];
    __shared__ int   si[4][CAND];
    __shared__ int   sn[4][SHORT];
    const int wid = threadIdx.x >> 5, lane = threadIdx.x & 31;
    const int b = blockIdx.x * 4 + wid;
    if (b >= B) return;

    for (int i = lane; i < CAND; i += 32) {
        sk[wid][i] = g_keys[(size_t)b * CAND + i];
        si[wid][i] = g_idxs[(size_t)b * CAND + i];
    }
    __syncwarp();

    for (int t = 0; t < SHORT; t++) {
        float bk = CUDART_INF_F; int bi = 0x7fffffff; int bp = -1;
        for (int i = lane; i < CAND; i += 32) {
            float kk = sk[wid][i]; int ii = si[wid][i];
            if (kk < bk || (kk == bk && ii < bi)) { bk = kk; bi = ii; bp = i; }
        }
        #pragma unroll
        for (int o = 16; o; o >>= 1) {
            float ok = __shfl_xor_sync(0xffffffffu, bk, o);
            int   oi = __shfl_xor_sync(0xffffffffu, bi, o);
            int   op = __shfl_xor_sync(0xffffffffu, bp, o);
            if (ok < bk || (ok == bk && oi < bi)) { bk = ok; bi = oi; bp = op; }
        }
        if (lane == 0) { sn[wid][t] = bi; sk[wid][bp] = CUDART_INF_F; }
        __syncwarp();
    }

    const float4 qv = *(const float4*)(xt + (size_t)b * DIM + lane * 4);
    float q2 = qv.x * qv.x + qv.y * qv.y + qv.z * qv.z + qv.w * qv.w;
    #pragma unroll
    for (int o = 16; o; o >>= 1) q2 += __shfl_xor_sync(0xffffffffu, q2, o);

    float keyA[SHORT], ddA[SHORT], wA[SHORT]; int nA[SHORT];
    const float wmax = g_wmax;
    for (int t = 0; t < SHORT; t++) {
        const int n = sn[wid][t];
        const float4 xv = *(const float4*)(X + (size_t)n * DIM + lane * 4);
        float dp = 0.0f, xp = 0.0f;
        dp = fmaf(qv.x, xv.x, dp); dp = fmaf(qv.y, xv.y, dp);
        dp = fmaf(qv.z, xv.z, dp); dp = fmaf(qv.w, xv.w, dp);
        xp = fmaf(xv.x, xv.x, xp); xp = fmaf(xv.y, xv.y, xp);
        xp = fmaf(xv.z, xv.z, xp); xp = fmaf(xv.w, xv.w, xp);
        #pragma unroll
        for (int o = 16; o; o >>= 1) {
            dp += __shfl_xor_sync(0xffffffffu, dp, o);
            xp += __shfl_xor_sync(0xffffffffu, xp, o);
        }
        if (lane == 0) {
            const float wn = w[n];
            const float dd = q2 - 2.0f * dp + xp;
            ddA[t] = dd; keyA[t] = dd + (wmax - wn); wA[t] = wn; nA[t] = n;
        }
    }

    if (lane == 0) {
        bool used[SHORT];
        #pragma unroll
        for (int t = 0; t < SHORT; t++) used[t] = false;
        float bestF = -CUDART_INF_F; int bestI = 0;
        for (int r = 0; r < KSEL; r++) {
            int pm = -1; float mkv = CUDART_INF_F; int miv = 0x7fffffff;
            for (int t = 0; t < SHORT; t++) {
                if (!used[t] && (keyA[t] < mkv || (keyA[t] == mkv && nA[t] < miv))) {
                    mkv = keyA[t]; miv = nA[t]; pm = t;
                }
            }
            if (pm < 0) break;
            used[pm] = true;
            const float f = wA[pm] - sqrtf(fmaxf(ddA[pm], 0.0f));
            if (f > bestF) { bestF = f; bestI = nA[pm]; }
        }
        out[b] = bestF;
        if (out_size >= 2 * B) out[B + b] = (float)bestI;
    }
}

// ---------------- entry ----------------
extern "C" void kernel_launch(void* const* d_in, const int* in_sizes, int n_in,
                              void* d_out, int out_size) {
    const float* xt = (const float*)d_in[0];
    const float* X  = (const float*)d_in[1];
    const float* w  = (const float*)d_in[2];
    const int B = in_sizes[0] / DIM;
    const int N = in_sizes[1] / DIM;

    const int per = (N + NSPLIT - 1) / NSPLIT;
    const int ntiles = (per + NB - 1) / NB;
    int padn = (NSPLIT - 1) * per + ntiles * NB;
    if (padn > MAXNP) padn = MAXNP;

    static bool once = false;
    if (!once) {
        cudaFuncSetAttribute(topk_kernel, cudaFuncAttributeMaxDynamicSharedMemorySize, SMEM_DYN);
        once = true;
    }

    init_kernel<<<1, 1>>>();
    wmax_kernel<<<160, 256>>>(w, N);
    prep_kernel<<<(padn + 255) / 256, 256>>>(X, w, N, padn);
    dim3 grid(B / QB, NSPLIT);
    topk_kernel<<<grid, NT, SMEM_DYN>>>(xt, per, ntiles);
    merge_kernel<<<(B + 3) / 4, 128>>>(xt, X, w, (float*)d_out, B, out_size);
}